// round 13
// baseline (speedup 1.0000x reference)
#include <cuda_runtime.h>
#include <cuda_fp16.h>
#include <cstdint>

// GeometricEdgeConv v10:
//  prepass: persistent HMMA y = x @ [Ws | We_feat]; weights converted
//           fp32->fp16 in-CTA (no prepack launch); aug fill inline.
//  gather:  1 warp = 2 points, 32-deep batched edge loads; HADD2 pairwise
//           first reduce level (error budget checked); pos weights via L1.

namespace {

constexpr int Nn = 16384;

constexpr int KH = 136;
constexpr int RB = KH * 2;                 // 272 B row (LDSM conflict-free)
constexpr int SM_B2 = 0;
constexpr int SM_A2 = 256 * RB;
constexpr int SM_Y  = SM_A2 + 128 * RB;
constexpr int YSTR  = 264;
constexpr int SM2_TOTAL = SM_Y + 128 * YSTR * 2;   // 172032

__device__ __half g_y[(size_t)131072 * 256];       // 64 MB scratch
__device__ float  g_aug[(size_t)131072 * 4];       // pos + |pos|^2

__device__ __forceinline__ uint32_t smem_u32(const void* p) {
    uint32_t a;
    asm("{ .reg .u64 t; cvta.to.shared.u64 t, %1; cvt.u32.u64 %0, t; }" : "=r"(a) : "l"(p));
    return a;
}
__device__ __forceinline__ uint32_t cvt2h(float a, float b) {  // lo=a, hi=b
    uint32_t r;
    asm("cvt.rn.f16x2.f32 %0, %1, %2;" : "=r"(r) : "f"(b), "f"(a));
    return r;
}
__device__ __forceinline__ void sts32(uint32_t addr, uint32_t v) {
    asm volatile("st.shared.b32 [%0], %1;" :: "r"(addr), "r"(v) : "memory");
}
__device__ __forceinline__ void sts64(uint32_t addr, uint32_t a, uint32_t b) {
    asm volatile("st.shared.v2.b32 [%0], {%1,%2};" :: "r"(addr), "r"(a), "r"(b) : "memory");
}
__device__ __forceinline__ void lds128(uint32_t addr, uint32_t* r) {
    asm volatile("ld.shared.v4.b32 {%0,%1,%2,%3}, [%4];"
                 : "=r"(r[0]), "=r"(r[1]), "=r"(r[2]), "=r"(r[3]) : "r"(addr));
}
__device__ __forceinline__ void ldsm_x4(uint32_t addr, uint32_t* r) {
    asm volatile("ldmatrix.sync.aligned.m8n8.x4.shared.b16 {%0,%1,%2,%3}, [%4];"
                 : "=r"(r[0]), "=r"(r[1]), "=r"(r[2]), "=r"(r[3]) : "r"(addr));
}
__device__ __forceinline__ void mma_f16(float* c, const uint32_t* a,
                                        uint32_t b0, uint32_t b1) {
    asm volatile(
        "mma.sync.aligned.m16n8k16.row.col.f32.f16.f16.f32 "
        "{%0,%1,%2,%3}, {%4,%5,%6,%7}, {%8,%9}, {%0,%1,%2,%3};"
        : "+f"(c[0]), "+f"(c[1]), "+f"(c[2]), "+f"(c[3])
        : "r"(a[0]), "r"(a[1]), "r"(a[2]), "r"(a[3]), "r"(b0), "r"(b1));
}

// ------------------------------------------------ prepass (fused prepack)
__global__ __launch_bounds__(512, 1) void prepass(
    const float* __restrict__ x, const float* __restrict__ pos,
    const float* __restrict__ ws, const float* __restrict__ we)
{
    extern __shared__ __align__(16) char sm[];
    const uint32_t smb = smem_u32(sm);
    const int tid = threadIdx.x, wid = tid >> 5, lane = tid & 31;

    // --- stage W2^T fp32->fp16 transposed, once per CTA (v6-verified) ---
    for (int i = tid; i < 64 * 256; i += 512) {
        int k2 = i >> 8, n = i & 255, k = k2 * 2;
        float va = (n < 128) ? ws[k * 128 + n] : we[k * 128 + (n - 128)];
        float vb = (n < 128) ? ws[(k + 1) * 128 + n] : we[(k + 1) * 128 + (n - 128)];
        sts32(smb + SM_B2 + n * RB + k2 * 4, cvt2h(va, vb));
    }
    for (int i = tid; i < 256 * 4; i += 512) {          // zero pad k=128..135
        int n = i >> 2, q = i & 3;
        sts32(smb + SM_B2 + n * RB + 256 + q * 4, 0u);
    }
    __syncthreads();

    const int g8 = lane >> 3, r8 = lane & 7;
    const uint32_t a_off = (uint32_t)(((g8 & 1) * 8 + r8) * RB + (g8 >> 1) * 16);
    const uint32_t b_off = (uint32_t)(((g8 >> 1) * 8 + r8) * RB + (g8 & 1) * 16);
    const int mg = wid >> 2, ng = wid & 3;

    for (int tile = blockIdx.x; tile < 1024; tile += gridDim.x) {
        const int tp0 = tile * 128;

        // aug rows for this tile (v6-verified)
        if (tid < 128) {
            int p = tp0 + tid;
            float px = pos[(size_t)p * 3], py = pos[(size_t)p * 3 + 1],
                  pz = pos[(size_t)p * 3 + 2];
            *(float4*)(g_aug + (size_t)p * 4) =
                make_float4(px, py, pz, px * px + py * py + pz * pz);
        }

        #pragma unroll
        for (int it = 0; it < 8; ++it) {
            int j = tid + it * 512;
            int row = j >> 5, c4 = j & 31;
            float4 f = *(const float4*)(x + (size_t)(tp0 + row) * 128 + c4 * 4);
            sts64(smb + SM_A2 + row * RB + c4 * 8, cvt2h(f.x, f.y), cvt2h(f.z, f.w));
        }
        __syncthreads();

        float c[2][8][4];
        #pragma unroll
        for (int mt = 0; mt < 2; ++mt)
            #pragma unroll
            for (int nt = 0; nt < 8; ++nt)
                #pragma unroll
                for (int q = 0; q < 4; ++q) c[mt][nt][q] = 0.f;

        const uint32_t Ab = smb + SM_A2 + (uint32_t)(mg * 32) * RB + a_off;
        const uint32_t Bb = smb + SM_B2 + (uint32_t)(ng * 64) * RB + b_off;
        #pragma unroll
        for (int kt = 0; kt < 8; ++kt) {
            uint32_t af[2][4], bf[4][4];
            ldsm_x4(Ab + kt * 32, af[0]);
            ldsm_x4(Ab + 16 * RB + kt * 32, af[1]);
            #pragma unroll
            for (int nn = 0; nn < 4; ++nn)
                ldsm_x4(Bb + (uint32_t)(nn * 16) * RB + kt * 32, bf[nn]);
            #pragma unroll
            for (int mt = 0; mt < 2; ++mt)
                #pragma unroll
                for (int nn = 0; nn < 4; ++nn) {
                    mma_f16(c[mt][nn * 2],     af[mt], bf[nn][0], bf[nn][1]);
                    mma_f16(c[mt][nn * 2 + 1], af[mt], bf[nn][2], bf[nn][3]);
                }
        }

        #pragma unroll
        for (int mt = 0; mt < 2; ++mt)
            #pragma unroll
            for (int nt = 0; nt < 8; ++nt) {
                int row = mg * 32 + mt * 16 + (lane >> 2);
                int col = ng * 64 + nt * 8 + 2 * (lane & 3);
                uint32_t ad = smb + SM_Y + (uint32_t)row * (YSTR * 2) + col * 2;
                sts32(ad, cvt2h(c[mt][nt][0], c[mt][nt][1]));
                sts32(ad + 8 * (YSTR * 2), cvt2h(c[mt][nt][2], c[mt][nt][3]));
            }
        __syncthreads();

        char* yt = (char*)(g_y + (size_t)tp0 * 256);
        #pragma unroll
        for (int it = 0; it < 8; ++it) {
            int j = tid + it * 512;
            int row = j >> 5, c16 = j & 31;
            uint32_t u[4];
            lds128(smb + SM_Y + (uint32_t)row * (YSTR * 2) + c16 * 16, u);
            *(uint4*)(yt + (size_t)row * 512 + c16 * 16) =
                make_uint4(u[0], u[1], u[2], u[3]);
        }
        __syncthreads();
    }
}

// -------------------------------- gather: 1 warp = 2 points
__global__ __launch_bounds__(256) void gather(
    const int* __restrict__ idx, const float* __restrict__ we,
    float* __restrict__ out)
{
    const int tid = threadIdx.x;
    const int warp = tid >> 5, lane = tid & 31;
    const int pA = (int)blockIdx.x * 16 + warp * 2;
    const int pB = pA + 1;
    const int b = pA >> 14;
    const __half* yb = g_y + ((size_t)b << 14) * 256;
    const float* augb = g_aug + ((size_t)b << 14) * 4;
    const float inv = 1.0f / 16.0f;

    int my = __ldg(idx + (size_t)pA * 16 + lane);      // lanes 0-15:A, 16-31:B

    // ---- issue ALL 32 edge-row loads before reduction (MLP=32) ----
    uint2 vA[16], vB[16];
    #pragma unroll
    for (int k = 0; k < 16; ++k) {
        int jA = __shfl_sync(0xffffffffu, my, k);
        vA[k] = *(const uint2*)(yb + (size_t)jA * 256 + 128 + lane * 4);
    }
    #pragma unroll
    for (int k = 0; k < 16; ++k) {
        int jB = __shfl_sync(0xffffffffu, my, 16 + k);
        vB[k] = *(const uint2*)(yb + (size_t)jB * 256 + 128 + lane * 4);
    }

    float4 av = *(const float4*)(augb + (size_t)my * 4);
    uint2 svA = *(const uint2*)(g_y + (size_t)pA * 256 + lane * 4);
    uint2 svB = *(const uint2*)(g_y + (size_t)pB * 256 + lane * 4);

    // pos weights (L1-resident, per-warp redundant)
    float4 w0 = __ldg((const float4*)(we + 128 * 128       + 4 * lane));
    float4 w1 = __ldg((const float4*)(we + 128 * 128 + 128 + 4 * lane));
    float4 w2 = __ldg((const float4*)(we + 128 * 128 + 256 + 4 * lane));
    float4 w3 = __ldg((const float4*)(we + 128 * 128 + 384 + 4 * lane));

    // ---- reduce: one HADD2 pairing level, then fp32 (err ~1.2e-4) ----
    float aA0 = 0.f, aA1 = 0.f, aA2 = 0.f, aA3 = 0.f;
    float aB0 = 0.f, aB1 = 0.f, aB2 = 0.f, aB3 = 0.f;
    #pragma unroll
    for (int t = 0; t < 8; ++t) {
        __half2 pAx = __hadd2(*(__half2*)&vA[2 * t].x, *(__half2*)&vA[2 * t + 1].x);
        __half2 pAy = __hadd2(*(__half2*)&vA[2 * t].y, *(__half2*)&vA[2 * t + 1].y);
        __half2 pBx = __hadd2(*(__half2*)&vB[2 * t].x, *(__half2*)&vB[2 * t + 1].x);
        __half2 pBy = __hadd2(*(__half2*)&vB[2 * t].y, *(__half2*)&vB[2 * t + 1].y);
        float2 fA0 = __half22float2(pAx);
        float2 fA1 = __half22float2(pAy);
        float2 fB0 = __half22float2(pBx);
        float2 fB1 = __half22float2(pBy);
        aA0 += fA0.x; aA1 += fA0.y; aA2 += fA1.x; aA3 += fA1.y;
        aB0 += fB0.x; aB1 += fB0.y; aB2 += fB1.x; aB3 += fB1.y;
    }

    // ---- aug means (half-warp reductions) ----
    float m0 = av.x, m1 = av.y, m2 = av.z, m3 = av.w;
    #pragma unroll
    for (int o = 8; o >= 1; o >>= 1) {
        m0 += __shfl_xor_sync(0xffffffffu, m0, o);
        m1 += __shfl_xor_sync(0xffffffffu, m1, o);
        m2 += __shfl_xor_sync(0xffffffffu, m2, o);
        m3 += __shfl_xor_sync(0xffffffffu, m3, o);
    }
    float mA0 = __shfl_sync(0xffffffffu, m0, 0) * inv;
    float mA1 = __shfl_sync(0xffffffffu, m1, 0) * inv;
    float mA2 = __shfl_sync(0xffffffffu, m2, 0) * inv;
    float mA3 = __shfl_sync(0xffffffffu, m3, 0) * inv;
    float mB0 = __shfl_sync(0xffffffffu, m0, 16) * inv;
    float mB1 = __shfl_sync(0xffffffffu, m1, 16) * inv;
    float mB2 = __shfl_sync(0xffffffffu, m2, 16) * inv;
    float mB3 = __shfl_sync(0xffffffffu, m3, 16) * inv;

    float4 asA = *(const float4*)(g_aug + (size_t)pA * 4);
    float4 asB = *(const float4*)(g_aug + (size_t)pB * 4);
    float rA0 = asA.x - mA0, rA1 = asA.y - mA1, rA2 = asA.z - mA2;
    float dsA = asA.w - 2.f * (asA.x * mA0 + asA.y * mA1 + asA.z * mA2) + mA3;
    float rB0 = asB.x - mB0, rB1 = asB.y - mB1, rB2 = asB.z - mB2;
    float dsB = asB.w - 2.f * (asB.x * mB0 + asB.y * mB1 + asB.z * mB2) + mB3;

    float2 sA0 = __half22float2(*(__half2*)&svA.x);
    float2 sA1 = __half22float2(*(__half2*)&svA.y);
    float2 sB0 = __half22float2(*(__half2*)&svB.x);
    float2 sB1 = __half22float2(*(__half2*)&svB.y);

    float v0 = sA0.x + aA0 * inv + rA0 * w0.x + rA1 * w1.x + rA2 * w2.x + dsA * w3.x;
    float v1 = sA0.y + aA1 * inv + rA0 * w0.y + rA1 * w1.y + rA2 * w2.y + dsA * w3.y;
    float v2 = sA1.x + aA2 * inv + rA0 * w0.z + rA1 * w1.z + rA2 * w2.z + dsA * w3.z;
    float v3 = sA1.y + aA3 * inv + rA0 * w0.w + rA1 * w1.w + rA2 * w2.w + dsA * w3.w;
    float4 rA;
    rA.x = v0 > 0.f ? v0 : 0.2f * v0;
    rA.y = v1 > 0.f ? v1 : 0.2f * v1;
    rA.z = v2 > 0.f ? v2 : 0.2f * v2;
    rA.w = v3 > 0.f ? v3 : 0.2f * v3;
    __stcs((float4*)(out + (size_t)pA * 128 + 4 * lane), rA);

    float u0 = sB0.x + aB0 * inv + rB0 * w0.x + rB1 * w1.x + rB2 * w2.x + dsB * w3.x;
    float u1 = sB0.y + aB1 * inv + rB0 * w0.y + rB1 * w1.y + rB2 * w2.y + dsB * w3.y;
    float u2 = sB1.x + aB2 * inv + rB0 * w0.z + rB1 * w1.z + rB2 * w2.z + dsB * w3.z;
    float u3 = sB1.y + aB3 * inv + rB0 * w0.w + rB1 * w1.w + rB2 * w2.w + dsB * w3.w;
    float4 rB;
    rB.x = u0 > 0.f ? u0 : 0.2f * u0;
    rB.y = u1 > 0.f ? u1 : 0.2f * u1;
    rB.z = u2 > 0.f ? u2 : 0.2f * u2;
    rB.w = u3 > 0.f ? u3 : 0.2f * u3;
    __stcs((float4*)(out + (size_t)pB * 128 + 4 * lane), rB);
}

}  // namespace

extern "C" void kernel_launch(void* const* d_in, const int* in_sizes, int n_in,
                              void* d_out, int out_size) {
    const float* x   = (const float*)d_in[0];   // [8,16384,128]
    const float* pos = (const float*)d_in[1];   // [8,16384,3]
    const int*   idx = (const int*)d_in[2];     // [8,16384,16]
    const float* ws  = (const float*)d_in[3];   // [128,128]
    const float* we  = (const float*)d_in[4];   // [132,128]
    float* out = (float*)d_out;

    cudaFuncSetAttribute(prepass, cudaFuncAttributeMaxDynamicSharedMemorySize, SM2_TOTAL);
    prepass<<<148, 512, SM2_TOTAL>>>(x, pos, ws, we);
    gather<<<8192, 256>>>(idx, we, out);
}

// round 14
// speedup vs baseline: 1.0190x; 1.0190x over previous
#include <cuda_runtime.h>
#include <cuda_fp16.h>
#include <cstdint>

// GeometricEdgeConv v11: best-of-breed recombination.
//  prepack: W2^T fp16 table + aug fill  (separate launch -- round-13 showed
//           fusing the conversion into the persistent prepass costs ~25us:
//           148 CTAs each re-transposing 133KB of fp32 weights).
//  prepass: v4-exact persistent HMMA y = x @ [Ws | We_feat]  (~28us).
//  gather:  round-13 version verbatim (59.7us): 1 warp = 2 points, 32-deep
//           batched edge loads, HADD2 pairwise reduce, pos weights via L1.

namespace {

constexpr int Nn = 16384;

constexpr int KH = 136;
constexpr int RB = KH * 2;                 // 272 B row (LDSM conflict-free)
constexpr int SM_B2 = 0;
constexpr int SM_A2 = 256 * RB;
constexpr int SM_Y  = SM_A2 + 128 * RB;
constexpr int YSTR  = 264;
constexpr int SM2_TOTAL = SM_Y + 128 * YSTR * 2;   // 172032

__device__ __half g_wt2[256 * KH];
__device__ __half g_y[(size_t)131072 * 256];       // 64 MB scratch
__device__ float  g_aug[(size_t)131072 * 4];       // pos + |pos|^2

__device__ __forceinline__ uint32_t smem_u32(const void* p) {
    uint32_t a;
    asm("{ .reg .u64 t; cvta.to.shared.u64 t, %1; cvt.u32.u64 %0, t; }" : "=r"(a) : "l"(p));
    return a;
}
__device__ __forceinline__ uint32_t cvt2h(float a, float b) {  // lo=a, hi=b
    uint32_t r;
    asm("cvt.rn.f16x2.f32 %0, %1, %2;" : "=r"(r) : "f"(b), "f"(a));
    return r;
}
__device__ __forceinline__ void sts32(uint32_t addr, uint32_t v) {
    asm volatile("st.shared.b32 [%0], %1;" :: "r"(addr), "r"(v) : "memory");
}
__device__ __forceinline__ void sts64(uint32_t addr, uint32_t a, uint32_t b) {
    asm volatile("st.shared.v2.b32 [%0], {%1,%2};" :: "r"(addr), "r"(a), "r"(b) : "memory");
}
__device__ __forceinline__ void lds128(uint32_t addr, uint32_t* r) {
    asm volatile("ld.shared.v4.b32 {%0,%1,%2,%3}, [%4];"
                 : "=r"(r[0]), "=r"(r[1]), "=r"(r[2]), "=r"(r[3]) : "r"(addr));
}
__device__ __forceinline__ void ldsm_x4(uint32_t addr, uint32_t* r) {
    asm volatile("ldmatrix.sync.aligned.m8n8.x4.shared.b16 {%0,%1,%2,%3}, [%4];"
                 : "=r"(r[0]), "=r"(r[1]), "=r"(r[2]), "=r"(r[3]) : "r"(addr));
}
__device__ __forceinline__ void mma_f16(float* c, const uint32_t* a,
                                        uint32_t b0, uint32_t b1) {
    asm volatile(
        "mma.sync.aligned.m16n8k16.row.col.f32.f16.f16.f32 "
        "{%0,%1,%2,%3}, {%4,%5,%6,%7}, {%8,%9}, {%0,%1,%2,%3};"
        : "+f"(c[0]), "+f"(c[1]), "+f"(c[2]), "+f"(c[3])
        : "r"(a[0]), "r"(a[1]), "r"(a[2]), "r"(a[3]), "r"(b0), "r"(b1));
}

// ------------------------------------------------ prepack (+ aug fill)
__global__ void prepack(const float* __restrict__ ws, const float* __restrict__ we,
                        const float* __restrict__ pos) {
    if (blockIdx.x < 136) {
        int t = blockIdx.x * 256 + threadIdx.x;
        if (t >= 256 * KH) return;
        int n = t / KH, k = t % KH;
        float v = 0.f;
        if (k < 128) v = (n < 128) ? ws[k * 128 + n] : we[k * 128 + (n - 128)];
        g_wt2[t] = __float2half_rn(v);
    } else {
        int i = (blockIdx.x - 136) * 256 + threadIdx.x;
        if (i >= 131072) return;
        float px = pos[(size_t)i * 3], py = pos[(size_t)i * 3 + 1],
              pz = pos[(size_t)i * 3 + 2];
        *(float4*)(g_aug + (size_t)i * 4) =
            make_float4(px, py, pz, px * px + py * py + pz * pz);
    }
}

// ------------------------------------------------ prepass (v4-exact)
__global__ __launch_bounds__(512, 1) void prepass(const float* __restrict__ x) {
    extern __shared__ __align__(16) char sm[];
    const uint32_t smb = smem_u32(sm);
    const int tid = threadIdx.x, wid = tid >> 5, lane = tid & 31;

    {
        const int4* s = (const int4*)g_wt2;
        int4* d = (int4*)(sm + SM_B2);
        for (int i = tid; i < 256 * RB / 16; i += 512) d[i] = s[i];
    }
    __syncthreads();

    const int g8 = lane >> 3, r8 = lane & 7;
    const uint32_t a_off = (uint32_t)(((g8 & 1) * 8 + r8) * RB + (g8 >> 1) * 16);
    const uint32_t b_off = (uint32_t)(((g8 >> 1) * 8 + r8) * RB + (g8 & 1) * 16);
    const int mg = wid >> 2, ng = wid & 3;

    for (int tile = blockIdx.x; tile < 1024; tile += gridDim.x) {
        const int tp0 = tile * 128;

        #pragma unroll
        for (int it = 0; it < 8; ++it) {
            int j = tid + it * 512;
            int row = j >> 5, c4 = j & 31;
            float4 f = *(const float4*)(x + (size_t)(tp0 + row) * 128 + c4 * 4);
            sts64(smb + SM_A2 + row * RB + c4 * 8, cvt2h(f.x, f.y), cvt2h(f.z, f.w));
        }
        __syncthreads();

        float c[2][8][4];
        #pragma unroll
        for (int mt = 0; mt < 2; ++mt)
            #pragma unroll
            for (int nt = 0; nt < 8; ++nt)
                #pragma unroll
                for (int q = 0; q < 4; ++q) c[mt][nt][q] = 0.f;

        const uint32_t Ab = smb + SM_A2 + (uint32_t)(mg * 32) * RB + a_off;
        const uint32_t Bb = smb + SM_B2 + (uint32_t)(ng * 64) * RB + b_off;
        #pragma unroll
        for (int kt = 0; kt < 8; ++kt) {
            uint32_t af[2][4], bf[4][4];
            ldsm_x4(Ab + kt * 32, af[0]);
            ldsm_x4(Ab + 16 * RB + kt * 32, af[1]);
            #pragma unroll
            for (int nn = 0; nn < 4; ++nn)
                ldsm_x4(Bb + (uint32_t)(nn * 16) * RB + kt * 32, bf[nn]);
            #pragma unroll
            for (int mt = 0; mt < 2; ++mt)
                #pragma unroll
                for (int nn = 0; nn < 4; ++nn) {
                    mma_f16(c[mt][nn * 2],     af[mt], bf[nn][0], bf[nn][1]);
                    mma_f16(c[mt][nn * 2 + 1], af[mt], bf[nn][2], bf[nn][3]);
                }
        }

        #pragma unroll
        for (int mt = 0; mt < 2; ++mt)
            #pragma unroll
            for (int nt = 0; nt < 8; ++nt) {
                int row = mg * 32 + mt * 16 + (lane >> 2);
                int col = ng * 64 + nt * 8 + 2 * (lane & 3);
                uint32_t ad = smb + SM_Y + (uint32_t)row * (YSTR * 2) + col * 2;
                sts32(ad, cvt2h(c[mt][nt][0], c[mt][nt][1]));
                sts32(ad + 8 * (YSTR * 2), cvt2h(c[mt][nt][2], c[mt][nt][3]));
            }
        __syncthreads();

        char* yt = (char*)(g_y + (size_t)tp0 * 256);
        #pragma unroll
        for (int it = 0; it < 8; ++it) {
            int j = tid + it * 512;
            int row = j >> 5, c16 = j & 31;
            uint32_t u[4];
            lds128(smb + SM_Y + (uint32_t)row * (YSTR * 2) + c16 * 16, u);
            *(uint4*)(yt + (size_t)row * 512 + c16 * 16) =
                make_uint4(u[0], u[1], u[2], u[3]);
        }
        __syncthreads();
    }
}

// -------------------------------- gather (round-13 version, 59.7us)
__global__ __launch_bounds__(256) void gather(
    const int* __restrict__ idx, const float* __restrict__ we,
    float* __restrict__ out)
{
    const int tid = threadIdx.x;
    const int warp = tid >> 5, lane = tid & 31;
    const int pA = (int)blockIdx.x * 16 + warp * 2;
    const int pB = pA + 1;
    const int b = pA >> 14;
    const __half* yb = g_y + ((size_t)b << 14) * 256;
    const float* augb = g_aug + ((size_t)b << 14) * 4;
    const float inv = 1.0f / 16.0f;

    int my = __ldg(idx + (size_t)pA * 16 + lane);      // lanes 0-15:A, 16-31:B

    // ---- issue ALL 32 edge-row loads before reduction (MLP=32) ----
    uint2 vA[16], vB[16];
    #pragma unroll
    for (int k = 0; k < 16; ++k) {
        int jA = __shfl_sync(0xffffffffu, my, k);
        vA[k] = *(const uint2*)(yb + (size_t)jA * 256 + 128 + lane * 4);
    }
    #pragma unroll
    for (int k = 0; k < 16; ++k) {
        int jB = __shfl_sync(0xffffffffu, my, 16 + k);
        vB[k] = *(const uint2*)(yb + (size_t)jB * 256 + 128 + lane * 4);
    }

    float4 av = *(const float4*)(augb + (size_t)my * 4);
    uint2 svA = *(const uint2*)(g_y + (size_t)pA * 256 + lane * 4);
    uint2 svB = *(const uint2*)(g_y + (size_t)pB * 256 + lane * 4);

    // pos weights (L1-resident, per-warp redundant)
    float4 w0 = __ldg((const float4*)(we + 128 * 128       + 4 * lane));
    float4 w1 = __ldg((const float4*)(we + 128 * 128 + 128 + 4 * lane));
    float4 w2 = __ldg((const float4*)(we + 128 * 128 + 256 + 4 * lane));
    float4 w3 = __ldg((const float4*)(we + 128 * 128 + 384 + 4 * lane));

    // ---- reduce: one HADD2 pairing level, then fp32 ----
    float aA0 = 0.f, aA1 = 0.f, aA2 = 0.f, aA3 = 0.f;
    float aB0 = 0.f, aB1 = 0.f, aB2 = 0.f, aB3 = 0.f;
    #pragma unroll
    for (int t = 0; t < 8; ++t) {
        __half2 pAx = __hadd2(*(__half2*)&vA[2 * t].x, *(__half2*)&vA[2 * t + 1].x);
        __half2 pAy = __hadd2(*(__half2*)&vA[2 * t].y, *(__half2*)&vA[2 * t + 1].y);
        __half2 pBx = __hadd2(*(__half2*)&vB[2 * t].x, *(__half2*)&vB[2 * t + 1].x);
        __half2 pBy = __hadd2(*(__half2*)&vB[2 * t].y, *(__half2*)&vB[2 * t + 1].y);
        float2 fA0 = __half22float2(pAx);
        float2 fA1 = __half22float2(pAy);
        float2 fB0 = __half22float2(pBx);
        float2 fB1 = __half22float2(pBy);
        aA0 += fA0.x; aA1 += fA0.y; aA2 += fA1.x; aA3 += fA1.y;
        aB0 += fB0.x; aB1 += fB0.y; aB2 += fB1.x; aB3 += fB1.y;
    }

    // ---- aug means (half-warp reductions) ----
    float m0 = av.x, m1 = av.y, m2 = av.z, m3 = av.w;
    #pragma unroll
    for (int o = 8; o >= 1; o >>= 1) {
        m0 += __shfl_xor_sync(0xffffffffu, m0, o);
        m1 += __shfl_xor_sync(0xffffffffu, m1, o);
        m2 += __shfl_xor_sync(0xffffffffu, m2, o);
        m3 += __shfl_xor_sync(0xffffffffu, m3, o);
    }
    float mA0 = __shfl_sync(0xffffffffu, m0, 0) * inv;
    float mA1 = __shfl_sync(0xffffffffu, m1, 0) * inv;
    float mA2 = __shfl_sync(0xffffffffu, m2, 0) * inv;
    float mA3 = __shfl_sync(0xffffffffu, m3, 0) * inv;
    float mB0 = __shfl_sync(0xffffffffu, m0, 16) * inv;
    float mB1 = __shfl_sync(0xffffffffu, m1, 16) * inv;
    float mB2 = __shfl_sync(0xffffffffu, m2, 16) * inv;
    float mB3 = __shfl_sync(0xffffffffu, m3, 16) * inv;

    float4 asA = *(const float4*)(g_aug + (size_t)pA * 4);
    float4 asB = *(const float4*)(g_aug + (size_t)pB * 4);
    float rA0 = asA.x - mA0, rA1 = asA.y - mA1, rA2 = asA.z - mA2;
    float dsA = asA.w - 2.f * (asA.x * mA0 + asA.y * mA1 + asA.z * mA2) + mA3;
    float rB0 = asB.x - mB0, rB1 = asB.y - mB1, rB2 = asB.z - mB2;
    float dsB = asB.w - 2.f * (asB.x * mB0 + asB.y * mB1 + asB.z * mB2) + mB3;

    float2 sA0 = __half22float2(*(__half2*)&svA.x);
    float2 sA1 = __half22float2(*(__half2*)&svA.y);
    float2 sB0 = __half22float2(*(__half2*)&svB.x);
    float2 sB1 = __half22float2(*(__half2*)&svB.y);

    float v0 = sA0.x + aA0 * inv + rA0 * w0.x + rA1 * w1.x + rA2 * w2.x + dsA * w3.x;
    float v1 = sA0.y + aA1 * inv + rA0 * w0.y + rA1 * w1.y + rA2 * w2.y + dsA * w3.y;
    float v2 = sA1.x + aA2 * inv + rA0 * w0.z + rA1 * w1.z + rA2 * w2.z + dsA * w3.z;
    float v3 = sA1.y + aA3 * inv + rA0 * w0.w + rA1 * w1.w + rA2 * w2.w + dsA * w3.w;
    float4 rA;
    rA.x = v0 > 0.f ? v0 : 0.2f * v0;
    rA.y = v1 > 0.f ? v1 : 0.2f * v1;
    rA.z = v2 > 0.f ? v2 : 0.2f * v2;
    rA.w = v3 > 0.f ? v3 : 0.2f * v3;
    __stcs((float4*)(out + (size_t)pA * 128 + 4 * lane), rA);

    float u0 = sB0.x + aB0 * inv + rB0 * w0.x + rB1 * w1.x + rB2 * w2.x + dsB * w3.x;
    float u1 = sB0.y + aB1 * inv + rB0 * w0.y + rB1 * w1.y + rB2 * w2.y + dsB * w3.y;
    float u2 = sB1.x + aB2 * inv + rB0 * w0.z + rB1 * w1.z + rB2 * w2.z + dsB * w3.z;
    float u3 = sB1.y + aB3 * inv + rB0 * w0.w + rB1 * w1.w + rB2 * w2.w + dsB * w3.w;
    float4 rB;
    rB.x = u0 > 0.f ? u0 : 0.2f * u0;
    rB.y = u1 > 0.f ? u1 : 0.2f * u1;
    rB.z = u2 > 0.f ? u2 : 0.2f * u2;
    rB.w = u3 > 0.f ? u3 : 0.2f * u3;
    __stcs((float4*)(out + (size_t)pB * 128 + 4 * lane), rB);
}

}  // namespace

extern "C" void kernel_launch(void* const* d_in, const int* in_sizes, int n_in,
                              void* d_out, int out_size) {
    const float* x   = (const float*)d_in[0];   // [8,16384,128]
    const float* pos = (const float*)d_in[1];   // [8,16384,3]
    const int*   idx = (const int*)d_in[2];     // [8,16384,16]
    const float* ws  = (const float*)d_in[3];   // [128,128]
    const float* we  = (const float*)d_in[4];   // [132,128]
    float* out = (float*)d_out;

    cudaFuncSetAttribute(prepass, cudaFuncAttributeMaxDynamicSharedMemorySize, SM2_TOTAL);
    prepack<<<136 + 512, 256>>>(ws, we, pos);
    prepass<<<148, 512, SM2_TOTAL>>>(x);
    gather<<<8192, 256>>>(idx, we, out);
}

// round 15
// speedup vs baseline: 1.1409x; 1.1196x over previous
#include <cuda_runtime.h>
#include <cuda_fp16.h>
#include <cstdint>

// GeometricEdgeConv v12:
//  prepack: W2^T fp16 table + aug fill (proven, 4.5us)
//  prepass: persistent HMMA y = x @ [Ws | We_feat], NOW software-pipelined:
//           next tile's x loads prefetched into registers across the MMA
//           phase (round-14 found prepass was ~48us = 38% of DRAM peak due
//           to phase serialization). Accumulators split into two n32 halves
//           to stay under the 128-reg cap.
//  gather:  round-13 version verbatim (59.7us).

namespace {

constexpr int Nn = 16384;

constexpr int KH = 136;
constexpr int RB = KH * 2;                 // 272 B row (LDSM conflict-free)
constexpr int SM_B2 = 0;
constexpr int SM_A2 = 256 * RB;
constexpr int SM_Y  = SM_A2 + 128 * RB;
constexpr int YSTR  = 264;
constexpr int SM2_TOTAL = SM_Y + 128 * YSTR * 2;   // 172032

__device__ __half g_wt2[256 * KH];
__device__ __half g_y[(size_t)131072 * 256];       // 64 MB scratch
__device__ float  g_aug[(size_t)131072 * 4];       // pos + |pos|^2

__device__ __forceinline__ uint32_t smem_u32(const void* p) {
    uint32_t a;
    asm("{ .reg .u64 t; cvta.to.shared.u64 t, %1; cvt.u32.u64 %0, t; }" : "=r"(a) : "l"(p));
    return a;
}
__device__ __forceinline__ uint32_t cvt2h(float a, float b) {  // lo=a, hi=b
    uint32_t r;
    asm("cvt.rn.f16x2.f32 %0, %1, %2;" : "=r"(r) : "f"(b), "f"(a));
    return r;
}
__device__ __forceinline__ void sts32(uint32_t addr, uint32_t v) {
    asm volatile("st.shared.b32 [%0], %1;" :: "r"(addr), "r"(v) : "memory");
}
__device__ __forceinline__ void sts64(uint32_t addr, uint32_t a, uint32_t b) {
    asm volatile("st.shared.v2.b32 [%0], {%1,%2};" :: "r"(addr), "r"(a), "r"(b) : "memory");
}
__device__ __forceinline__ void lds128(uint32_t addr, uint32_t* r) {
    asm volatile("ld.shared.v4.b32 {%0,%1,%2,%3}, [%4];"
                 : "=r"(r[0]), "=r"(r[1]), "=r"(r[2]), "=r"(r[3]) : "r"(addr));
}
__device__ __forceinline__ void ldsm_x4(uint32_t addr, uint32_t* r) {
    asm volatile("ldmatrix.sync.aligned.m8n8.x4.shared.b16 {%0,%1,%2,%3}, [%4];"
                 : "=r"(r[0]), "=r"(r[1]), "=r"(r[2]), "=r"(r[3]) : "r"(addr));
}
__device__ __forceinline__ void mma_f16(float* c, const uint32_t* a,
                                        uint32_t b0, uint32_t b1) {
    asm volatile(
        "mma.sync.aligned.m16n8k16.row.col.f32.f16.f16.f32 "
        "{%0,%1,%2,%3}, {%4,%5,%6,%7}, {%8,%9}, {%0,%1,%2,%3};"
        : "+f"(c[0]), "+f"(c[1]), "+f"(c[2]), "+f"(c[3])
        : "r"(a[0]), "r"(a[1]), "r"(a[2]), "r"(a[3]), "r"(b0), "r"(b1));
}

// ------------------------------------------------ prepack (+ aug fill)
__global__ void prepack(const float* __restrict__ ws, const float* __restrict__ we,
                        const float* __restrict__ pos) {
    if (blockIdx.x < 136) {
        int t = blockIdx.x * 256 + threadIdx.x;
        if (t >= 256 * KH) return;
        int n = t / KH, k = t % KH;
        float v = 0.f;
        if (k < 128) v = (n < 128) ? ws[k * 128 + n] : we[k * 128 + (n - 128)];
        g_wt2[t] = __float2half_rn(v);
    } else {
        int i = (blockIdx.x - 136) * 256 + threadIdx.x;
        if (i >= 131072) return;
        float px = pos[(size_t)i * 3], py = pos[(size_t)i * 3 + 1],
              pz = pos[(size_t)i * 3 + 2];
        *(float4*)(g_aug + (size_t)i * 4) =
            make_float4(px, py, pz, px * px + py * py + pz * pz);
    }
}

// ------------------------------------------------ prepass (pipelined)
__global__ __launch_bounds__(512, 1) void prepass(const float* __restrict__ x) {
    extern __shared__ __align__(16) char sm[];
    const uint32_t smb = smem_u32(sm);
    const int tid = threadIdx.x, wid = tid >> 5, lane = tid & 31;

    {
        const int4* s = (const int4*)g_wt2;
        int4* d = (int4*)(sm + SM_B2);
        for (int i = tid; i < 256 * RB / 16; i += 512) d[i] = s[i];
    }
    __syncthreads();

    const int g8 = lane >> 3, r8 = lane & 7;
    const uint32_t a_off = (uint32_t)(((g8 & 1) * 8 + r8) * RB + (g8 >> 1) * 16);
    const uint32_t b_off = (uint32_t)(((g8 >> 1) * 8 + r8) * RB + (g8 & 1) * 16);
    const int mg = wid >> 2, ng = wid & 3;

    // per-thread x-load coordinates: rows row0 + it*16, cols c4*4..+3
    const int row0 = tid >> 5;          // 0..15
    const int c4 = tid & 31;

    // ---- prologue: prefetch first tile into registers ----
    float4 xr[8];
    int tile = blockIdx.x;
    if (tile < 1024) {
        const float* xt = x + (size_t)tile * 128 * 128;
        #pragma unroll
        for (int it = 0; it < 8; ++it)
            xr[it] = *(const float4*)(xt + (size_t)(row0 + it * 16) * 128 + c4 * 4);
    }

    for (; tile < 1024; tile += gridDim.x) {
        const int tp0 = tile * 128;

        // ---- convert prefetched regs -> A smem ----
        #pragma unroll
        for (int it = 0; it < 8; ++it) {
            float4 f = xr[it];
            sts64(smb + SM_A2 + (row0 + it * 16) * RB + c4 * 8,
                  cvt2h(f.x, f.y), cvt2h(f.z, f.w));
        }
        __syncthreads();

        // ---- prefetch NEXT tile (overlaps the MMA below) ----
        const int ntile = tile + gridDim.x;
        if (ntile < 1024) {
            const float* xt = x + (size_t)ntile * 128 * 128;
            #pragma unroll
            for (int it = 0; it < 8; ++it)
                xr[it] = *(const float4*)(xt + (size_t)(row0 + it * 16) * 128 + c4 * 4);
        }

        // ---- MMA in two n32 halves (keeps regs under the 128 cap) ----
        const uint32_t Ab = smb + SM_A2 + (uint32_t)(mg * 32) * RB + a_off;
        #pragma unroll
        for (int hf = 0; hf < 2; ++hf) {
            float c[2][4][4];
            #pragma unroll
            for (int mt = 0; mt < 2; ++mt)
                #pragma unroll
                for (int nt = 0; nt < 4; ++nt)
                    #pragma unroll
                    for (int q = 0; q < 4; ++q) c[mt][nt][q] = 0.f;

            const uint32_t Bb = smb + SM_B2
                + (uint32_t)(ng * 64 + hf * 32) * RB + b_off;
            #pragma unroll
            for (int kt = 0; kt < 8; ++kt) {
                uint32_t af[2][4], bf[2][4];
                ldsm_x4(Ab + kt * 32, af[0]);
                ldsm_x4(Ab + 16 * RB + kt * 32, af[1]);
                ldsm_x4(Bb + kt * 32, bf[0]);
                ldsm_x4(Bb + 16 * RB + kt * 32, bf[1]);
                #pragma unroll
                for (int mt = 0; mt < 2; ++mt) {
                    mma_f16(c[mt][0], af[mt], bf[0][0], bf[0][1]);
                    mma_f16(c[mt][1], af[mt], bf[0][2], bf[0][3]);
                    mma_f16(c[mt][2], af[mt], bf[1][0], bf[1][1]);
                    mma_f16(c[mt][3], af[mt], bf[1][2], bf[1][3]);
                }
            }

            // stage this half's frags -> SM_Y (fp16)
            #pragma unroll
            for (int mt = 0; mt < 2; ++mt)
                #pragma unroll
                for (int nt = 0; nt < 4; ++nt) {
                    int row = mg * 32 + mt * 16 + (lane >> 2);
                    int col = ng * 64 + hf * 32 + nt * 8 + 2 * (lane & 3);
                    uint32_t ad = smb + SM_Y + (uint32_t)row * (YSTR * 2) + col * 2;
                    sts32(ad, cvt2h(c[mt][nt][0], c[mt][nt][1]));
                    sts32(ad + 8 * (YSTR * 2), cvt2h(c[mt][nt][2], c[mt][nt][3]));
                }
        }
        __syncthreads();

        // ---- coalesced y store ----
        char* yt = (char*)(g_y + (size_t)tp0 * 256);
        #pragma unroll
        for (int it = 0; it < 8; ++it) {
            int j = tid + it * 512;
            int row = j >> 5, c16 = j & 31;
            uint32_t u[4];
            lds128(smb + SM_Y + (uint32_t)row * (YSTR * 2) + c16 * 16, u);
            *(uint4*)(yt + (size_t)row * 512 + c16 * 16) =
                make_uint4(u[0], u[1], u[2], u[3]);
        }
        __syncthreads();
    }
}

// -------------------------------- gather (round-13 version, 59.7us)
__global__ __launch_bounds__(256) void gather(
    const int* __restrict__ idx, const float* __restrict__ we,
    float* __restrict__ out)
{
    const int tid = threadIdx.x;
    const int warp = tid >> 5, lane = tid & 31;
    const int pA = (int)blockIdx.x * 16 + warp * 2;
    const int pB = pA + 1;
    const int b = pA >> 14;
    const __half* yb = g_y + ((size_t)b << 14) * 256;
    const float* augb = g_aug + ((size_t)b << 14) * 4;
    const float inv = 1.0f / 16.0f;

    int my = __ldg(idx + (size_t)pA * 16 + lane);      // lanes 0-15:A, 16-31:B

    uint2 vA[16], vB[16];
    #pragma unroll
    for (int k = 0; k < 16; ++k) {
        int jA = __shfl_sync(0xffffffffu, my, k);
        vA[k] = *(const uint2*)(yb + (size_t)jA * 256 + 128 + lane * 4);
    }
    #pragma unroll
    for (int k = 0; k < 16; ++k) {
        int jB = __shfl_sync(0xffffffffu, my, 16 + k);
        vB[k] = *(const uint2*)(yb + (size_t)jB * 256 + 128 + lane * 4);
    }

    float4 av = *(const float4*)(augb + (size_t)my * 4);
    uint2 svA = *(const uint2*)(g_y + (size_t)pA * 256 + lane * 4);
    uint2 svB = *(const uint2*)(g_y + (size_t)pB * 256 + lane * 4);

    float4 w0 = __ldg((const float4*)(we + 128 * 128       + 4 * lane));
    float4 w1 = __ldg((const float4*)(we + 128 * 128 + 128 + 4 * lane));
    float4 w2 = __ldg((const float4*)(we + 128 * 128 + 256 + 4 * lane));
    float4 w3 = __ldg((const float4*)(we + 128 * 128 + 384 + 4 * lane));

    float aA0 = 0.f, aA1 = 0.f, aA2 = 0.f, aA3 = 0.f;
    float aB0 = 0.f, aB1 = 0.f, aB2 = 0.f, aB3 = 0.f;
    #pragma unroll
    for (int t = 0; t < 8; ++t) {
        __half2 pAx = __hadd2(*(__half2*)&vA[2 * t].x, *(__half2*)&vA[2 * t + 1].x);
        __half2 pAy = __hadd2(*(__half2*)&vA[2 * t].y, *(__half2*)&vA[2 * t + 1].y);
        __half2 pBx = __hadd2(*(__half2*)&vB[2 * t].x, *(__half2*)&vB[2 * t + 1].x);
        __half2 pBy = __hadd2(*(__half2*)&vB[2 * t].y, *(__half2*)&vB[2 * t + 1].y);
        float2 fA0 = __half22float2(pAx);
        float2 fA1 = __half22float2(pAy);
        float2 fB0 = __half22float2(pBx);
        float2 fB1 = __half22float2(pBy);
        aA0 += fA0.x; aA1 += fA0.y; aA2 += fA1.x; aA3 += fA1.y;
        aB0 += fB0.x; aB1 += fB0.y; aB2 += fB1.x; aB3 += fB1.y;
    }

    float m0 = av.x, m1 = av.y, m2 = av.z, m3 = av.w;
    #pragma unroll
    for (int o = 8; o >= 1; o >>= 1) {
        m0 += __shfl_xor_sync(0xffffffffu, m0, o);
        m1 += __shfl_xor_sync(0xffffffffu, m1, o);
        m2 += __shfl_xor_sync(0xffffffffu, m2, o);
        m3 += __shfl_xor_sync(0xffffffffu, m3, o);
    }
    float mA0 = __shfl_sync(0xffffffffu, m0, 0) * inv;
    float mA1 = __shfl_sync(0xffffffffu, m1, 0) * inv;
    float mA2 = __shfl_sync(0xffffffffu, m2, 0) * inv;
    float mA3 = __shfl_sync(0xffffffffu, m3, 0) * inv;
    float mB0 = __shfl_sync(0xffffffffu, m0, 16) * inv;
    float mB1 = __shfl_sync(0xffffffffu, m1, 16) * inv;
    float mB2 = __shfl_sync(0xffffffffu, m2, 16) * inv;
    float mB3 = __shfl_sync(0xffffffffu, m3, 16) * inv;

    float4 asA = *(const float4*)(g_aug + (size_t)pA * 4);
    float4 asB = *(const float4*)(g_aug + (size_t)pB * 4);
    float rA0 = asA.x - mA0, rA1 = asA.y - mA1, rA2 = asA.z - mA2;
    float dsA = asA.w - 2.f * (asA.x * mA0 + asA.y * mA1 + asA.z * mA2) + mA3;
    float rB0 = asB.x - mB0, rB1 = asB.y - mB1, rB2 = asB.z - mB2;
    float dsB = asB.w - 2.f * (asB.x * mB0 + asB.y * mB1 + asB.z * mB2) + mB3;

    float2 sA0 = __half22float2(*(__half2*)&svA.x);
    float2 sA1 = __half22float2(*(__half2*)&svA.y);
    float2 sB0 = __half22float2(*(__half2*)&svB.x);
    float2 sB1 = __half22float2(*(__half2*)&svB.y);

    float v0 = sA0.x + aA0 * inv + rA0 * w0.x + rA1 * w1.x + rA2 * w2.x + dsA * w3.x;
    float v1 = sA0.y + aA1 * inv + rA0 * w0.y + rA1 * w1.y + rA2 * w2.y + dsA * w3.y;
    float v2 = sA1.x + aA2 * inv + rA0 * w0.z + rA1 * w1.z + rA2 * w2.z + dsA * w3.z;
    float v3 = sA1.y + aA3 * inv + rA0 * w0.w + rA1 * w1.w + rA2 * w2.w + dsA * w3.w;
    float4 rA;
    rA.x = v0 > 0.f ? v0 : 0.2f * v0;
    rA.y = v1 > 0.f ? v1 : 0.2f * v1;
    rA.z = v2 > 0.f ? v2 : 0.2f * v2;
    rA.w = v3 > 0.f ? v3 : 0.2f * v3;
    __stcs((float4*)(out + (size_t)pA * 128 + 4 * lane), rA);

    float u0 = sB0.x + aB0 * inv + rB0 * w0.x + rB1 * w1.x + rB2 * w2.x + dsB * w3.x;
    float u1 = sB0.y + aB1 * inv + rB0 * w0.y + rB1 * w1.y + rB2 * w2.y + dsB * w3.y;
    float u2 = sB1.x + aB2 * inv + rB0 * w0.z + rB1 * w1.z + rB2 * w2.z + dsB * w3.z;
    float u3 = sB1.y + aB3 * inv + rB0 * w0.w + rB1 * w1.w + rB2 * w2.w + dsB * w3.w;
    float4 rB;
    rB.x = u0 > 0.f ? u0 : 0.2f * u0;
    rB.y = u1 > 0.f ? u1 : 0.2f * u1;
    rB.z = u2 > 0.f ? u2 : 0.2f * u2;
    rB.w = u3 > 0.f ? u3 : 0.2f * u3;
    __stcs((float4*)(out + (size_t)pB * 128 + 4 * lane), rB);
}

}  // namespace

extern "C" void kernel_launch(void* const* d_in, const int* in_sizes, int n_in,
                              void* d_out, int out_size) {
    const float* x   = (const float*)d_in[0];   // [8,16384,128]
    const float* pos = (const float*)d_in[1];   // [8,16384,3]
    const int*   idx = (const int*)d_in[2];     // [8,16384,16]
    const float* ws  = (const float*)d_in[3];   // [128,128]
    const float* we  = (const float*)d_in[4];   // [132,128]
    float* out = (float*)d_out;

    cudaFuncSetAttribute(prepass, cudaFuncAttributeMaxDynamicSharedMemorySize, SM2_TOTAL);
    prepack<<<136 + 512, 256>>>(ws, we, pos);
    prepass<<<148, 512, SM2_TOTAL>>>(x);
    gather<<<8192, 256>>>(idx, we, out);
}

// round 16
// speedup vs baseline: 1.1431x; 1.0019x over previous
#include <cuda_runtime.h>
#include <cuda_fp16.h>
#include <cstdint>

// GeometricEdgeConv v12:
//  prepack: W2^T fp16 table + aug fill (proven, 4.5us)
//  prepass: persistent HMMA y = x @ [Ws | We_feat], NOW software-pipelined:
//           next tile's x loads prefetched into registers across the MMA
//           phase (round-14 found prepass was ~48us = 38% of DRAM peak due
//           to phase serialization). Accumulators split into two n32 halves
//           to stay under the 128-reg cap.
//  gather:  round-13 version verbatim (59.7us).

namespace {

constexpr int Nn = 16384;

constexpr int KH = 136;
constexpr int RB = KH * 2;                 // 272 B row (LDSM conflict-free)
constexpr int SM_B2 = 0;
constexpr int SM_A2 = 256 * RB;
constexpr int SM_Y  = SM_A2 + 128 * RB;
constexpr int YSTR  = 264;
constexpr int SM2_TOTAL = SM_Y + 128 * YSTR * 2;   // 172032

__device__ __half g_wt2[256 * KH];
__device__ __half g_y[(size_t)131072 * 256];       // 64 MB scratch
__device__ float  g_aug[(size_t)131072 * 4];       // pos + |pos|^2

__device__ __forceinline__ uint32_t smem_u32(const void* p) {
    uint32_t a;
    asm("{ .reg .u64 t; cvta.to.shared.u64 t, %1; cvt.u32.u64 %0, t; }" : "=r"(a) : "l"(p));
    return a;
}
__device__ __forceinline__ uint32_t cvt2h(float a, float b) {  // lo=a, hi=b
    uint32_t r;
    asm("cvt.rn.f16x2.f32 %0, %1, %2;" : "=r"(r) : "f"(b), "f"(a));
    return r;
}
__device__ __forceinline__ void sts32(uint32_t addr, uint32_t v) {
    asm volatile("st.shared.b32 [%0], %1;" :: "r"(addr), "r"(v) : "memory");
}
__device__ __forceinline__ void sts64(uint32_t addr, uint32_t a, uint32_t b) {
    asm volatile("st.shared.v2.b32 [%0], {%1,%2};" :: "r"(addr), "r"(a), "r"(b) : "memory");
}
__device__ __forceinline__ void lds128(uint32_t addr, uint32_t* r) {
    asm volatile("ld.shared.v4.b32 {%0,%1,%2,%3}, [%4];"
                 : "=r"(r[0]), "=r"(r[1]), "=r"(r[2]), "=r"(r[3]) : "r"(addr));
}
__device__ __forceinline__ void ldsm_x4(uint32_t addr, uint32_t* r) {
    asm volatile("ldmatrix.sync.aligned.m8n8.x4.shared.b16 {%0,%1,%2,%3}, [%4];"
                 : "=r"(r[0]), "=r"(r[1]), "=r"(r[2]), "=r"(r[3]) : "r"(addr));
}
__device__ __forceinline__ void mma_f16(float* c, const uint32_t* a,
                                        uint32_t b0, uint32_t b1) {
    asm volatile(
        "mma.sync.aligned.m16n8k16.row.col.f32.f16.f16.f32 "
        "{%0,%1,%2,%3}, {%4,%5,%6,%7}, {%8,%9}, {%0,%1,%2,%3};"
        : "+f"(c[0]), "+f"(c[1]), "+f"(c[2]), "+f"(c[3])
        : "r"(a[0]), "r"(a[1]), "r"(a[2]), "r"(a[3]), "r"(b0), "r"(b1));
}

// ------------------------------------------------ prepack (+ aug fill)
__global__ void prepack(const float* __restrict__ ws, const float* __restrict__ we,
                        const float* __restrict__ pos) {
    if (blockIdx.x < 136) {
        int t = blockIdx.x * 256 + threadIdx.x;
        if (t >= 256 * KH) return;
        int n = t / KH, k = t % KH;
        float v = 0.f;
        if (k < 128) v = (n < 128) ? ws[k * 128 + n] : we[k * 128 + (n - 128)];
        g_wt2[t] = __float2half_rn(v);
    } else {
        int i = (blockIdx.x - 136) * 256 + threadIdx.x;
        if (i >= 131072) return;
        float px = pos[(size_t)i * 3], py = pos[(size_t)i * 3 + 1],
              pz = pos[(size_t)i * 3 + 2];
        *(float4*)(g_aug + (size_t)i * 4) =
            make_float4(px, py, pz, px * px + py * py + pz * pz);
    }
}

// ------------------------------------------------ prepass (pipelined)
__global__ __launch_bounds__(512, 1) void prepass(const float* __restrict__ x) {
    extern __shared__ __align__(16) char sm[];
    const uint32_t smb = smem_u32(sm);
    const int tid = threadIdx.x, wid = tid >> 5, lane = tid & 31;

    {
        const int4* s = (const int4*)g_wt2;
        int4* d = (int4*)(sm + SM_B2);
        for (int i = tid; i < 256 * RB / 16; i += 512) d[i] = s[i];
    }
    __syncthreads();

    const int g8 = lane >> 3, r8 = lane & 7;
    const uint32_t a_off = (uint32_t)(((g8 & 1) * 8 + r8) * RB + (g8 >> 1) * 16);
    const uint32_t b_off = (uint32_t)(((g8 >> 1) * 8 + r8) * RB + (g8 & 1) * 16);
    const int mg = wid >> 2, ng = wid & 3;

    // per-thread x-load coordinates: rows row0 + it*16, cols c4*4..+3
    const int row0 = tid >> 5;          // 0..15
    const int c4 = tid & 31;

    // ---- prologue: prefetch first tile into registers ----
    float4 xr[8];
    int tile = blockIdx.x;
    if (tile < 1024) {
        const float* xt = x + (size_t)tile * 128 * 128;
        #pragma unroll
        for (int it = 0; it < 8; ++it)
            xr[it] = *(const float4*)(xt + (size_t)(row0 + it * 16) * 128 + c4 * 4);
    }

    for (; tile < 1024; tile += gridDim.x) {
        const int tp0 = tile * 128;

        // ---- convert prefetched regs -> A smem ----
        #pragma unroll
        for (int it = 0; it < 8; ++it) {
            float4 f = xr[it];
            sts64(smb + SM_A2 + (row0 + it * 16) * RB + c4 * 8,
                  cvt2h(f.x, f.y), cvt2h(f.z, f.w));
        }
        __syncthreads();

        // ---- prefetch NEXT tile (overlaps the MMA below) ----
        const int ntile = tile + gridDim.x;
        if (ntile < 1024) {
            const float* xt = x + (size_t)ntile * 128 * 128;
            #pragma unroll
            for (int it = 0; it < 8; ++it)
                xr[it] = *(const float4*)(xt + (size_t)(row0 + it * 16) * 128 + c4 * 4);
        }

        // ---- MMA in two n32 halves (keeps regs under the 128 cap) ----
        const uint32_t Ab = smb + SM_A2 + (uint32_t)(mg * 32) * RB + a_off;
        #pragma unroll
        for (int hf = 0; hf < 2; ++hf) {
            float c[2][4][4];
            #pragma unroll
            for (int mt = 0; mt < 2; ++mt)
                #pragma unroll
                for (int nt = 0; nt < 4; ++nt)
                    #pragma unroll
                    for (int q = 0; q < 4; ++q) c[mt][nt][q] = 0.f;

            const uint32_t Bb = smb + SM_B2
                + (uint32_t)(ng * 64 + hf * 32) * RB + b_off;
            #pragma unroll
            for (int kt = 0; kt < 8; ++kt) {
                uint32_t af[2][4], bf[2][4];
                ldsm_x4(Ab + kt * 32, af[0]);
                ldsm_x4(Ab + 16 * RB + kt * 32, af[1]);
                ldsm_x4(Bb + kt * 32, bf[0]);
                ldsm_x4(Bb + 16 * RB + kt * 32, bf[1]);
                #pragma unroll
                for (int mt = 0; mt < 2; ++mt) {
                    mma_f16(c[mt][0], af[mt], bf[0][0], bf[0][1]);
                    mma_f16(c[mt][1], af[mt], bf[0][2], bf[0][3]);
                    mma_f16(c[mt][2], af[mt], bf[1][0], bf[1][1]);
                    mma_f16(c[mt][3], af[mt], bf[1][2], bf[1][3]);
                }
            }

            // stage this half's frags -> SM_Y (fp16)
            #pragma unroll
            for (int mt = 0; mt < 2; ++mt)
                #pragma unroll
                for (int nt = 0; nt < 4; ++nt) {
                    int row = mg * 32 + mt * 16 + (lane >> 2);
                    int col = ng * 64 + hf * 32 + nt * 8 + 2 * (lane & 3);
                    uint32_t ad = smb + SM_Y + (uint32_t)row * (YSTR * 2) + col * 2;
                    sts32(ad, cvt2h(c[mt][nt][0], c[mt][nt][1]));
                    sts32(ad + 8 * (YSTR * 2), cvt2h(c[mt][nt][2], c[mt][nt][3]));
                }
        }
        __syncthreads();

        // ---- coalesced y store ----
        char* yt = (char*)(g_y + (size_t)tp0 * 256);
        #pragma unroll
        for (int it = 0; it < 8; ++it) {
            int j = tid + it * 512;
            int row = j >> 5, c16 = j & 31;
            uint32_t u[4];
            lds128(smb + SM_Y + (uint32_t)row * (YSTR * 2) + c16 * 16, u);
            *(uint4*)(yt + (size_t)row * 512 + c16 * 16) =
                make_uint4(u[0], u[1], u[2], u[3]);
        }
        __syncthreads();
    }
}

// -------------------------------- gather (round-13 version, 59.7us)
__global__ __launch_bounds__(256) void gather(
    const int* __restrict__ idx, const float* __restrict__ we,
    float* __restrict__ out)
{
    const int tid = threadIdx.x;
    const int warp = tid >> 5, lane = tid & 31;
    const int pA = (int)blockIdx.x * 16 + warp * 2;
    const int pB = pA + 1;
    const int b = pA >> 14;
    const __half* yb = g_y + ((size_t)b << 14) * 256;
    const float* augb = g_aug + ((size_t)b << 14) * 4;
    const float inv = 1.0f / 16.0f;

    int my = __ldg(idx + (size_t)pA * 16 + lane);      // lanes 0-15:A, 16-31:B

    uint2 vA[16], vB[16];
    #pragma unroll
    for (int k = 0; k < 16; ++k) {
        int jA = __shfl_sync(0xffffffffu, my, k);
        vA[k] = *(const uint2*)(yb + (size_t)jA * 256 + 128 + lane * 4);
    }
    #pragma unroll
    for (int k = 0; k < 16; ++k) {
        int jB = __shfl_sync(0xffffffffu, my, 16 + k);
        vB[k] = *(const uint2*)(yb + (size_t)jB * 256 + 128 + lane * 4);
    }

    float4 av = *(const float4*)(augb + (size_t)my * 4);
    uint2 svA = *(const uint2*)(g_y + (size_t)pA * 256 + lane * 4);
    uint2 svB = *(const uint2*)(g_y + (size_t)pB * 256 + lane * 4);

    float4 w0 = __ldg((const float4*)(we + 128 * 128       + 4 * lane));
    float4 w1 = __ldg((const float4*)(we + 128 * 128 + 128 + 4 * lane));
    float4 w2 = __ldg((const float4*)(we + 128 * 128 + 256 + 4 * lane));
    float4 w3 = __ldg((const float4*)(we + 128 * 128 + 384 + 4 * lane));

    float aA0 = 0.f, aA1 = 0.f, aA2 = 0.f, aA3 = 0.f;
    float aB0 = 0.f, aB1 = 0.f, aB2 = 0.f, aB3 = 0.f;
    #pragma unroll
    for (int t = 0; t < 8; ++t) {
        __half2 pAx = __hadd2(*(__half2*)&vA[2 * t].x, *(__half2*)&vA[2 * t + 1].x);
        __half2 pAy = __hadd2(*(__half2*)&vA[2 * t].y, *(__half2*)&vA[2 * t + 1].y);
        __half2 pBx = __hadd2(*(__half2*)&vB[2 * t].x, *(__half2*)&vB[2 * t + 1].x);
        __half2 pBy = __hadd2(*(__half2*)&vB[2 * t].y, *(__half2*)&vB[2 * t + 1].y);
        float2 fA0 = __half22float2(pAx);
        float2 fA1 = __half22float2(pAy);
        float2 fB0 = __half22float2(pBx);
        float2 fB1 = __half22float2(pBy);
        aA0 += fA0.x; aA1 += fA0.y; aA2 += fA1.x; aA3 += fA1.y;
        aB0 += fB0.x; aB1 += fB0.y; aB2 += fB1.x; aB3 += fB1.y;
    }

    float m0 = av.x, m1 = av.y, m2 = av.z, m3 = av.w;
    #pragma unroll
    for (int o = 8; o >= 1; o >>= 1) {
        m0 += __shfl_xor_sync(0xffffffffu, m0, o);
        m1 += __shfl_xor_sync(0xffffffffu, m1, o);
        m2 += __shfl_xor_sync(0xffffffffu, m2, o);
        m3 += __shfl_xor_sync(0xffffffffu, m3, o);
    }
    float mA0 = __shfl_sync(0xffffffffu, m0, 0) * inv;
    float mA1 = __shfl_sync(0xffffffffu, m1, 0) * inv;
    float mA2 = __shfl_sync(0xffffffffu, m2, 0) * inv;
    float mA3 = __shfl_sync(0xffffffffu, m3, 0) * inv;
    float mB0 = __shfl_sync(0xffffffffu, m0, 16) * inv;
    float mB1 = __shfl_sync(0xffffffffu, m1, 16) * inv;
    float mB2 = __shfl_sync(0xffffffffu, m2, 16) * inv;
    float mB3 = __shfl_sync(0xffffffffu, m3, 16) * inv;

    float4 asA = *(const float4*)(g_aug + (size_t)pA * 4);
    float4 asB = *(const float4*)(g_aug + (size_t)pB * 4);
    float rA0 = asA.x - mA0, rA1 = asA.y - mA1, rA2 = asA.z - mA2;
    float dsA = asA.w - 2.f * (asA.x * mA0 + asA.y * mA1 + asA.z * mA2) + mA3;
    float rB0 = asB.x - mB0, rB1 = asB.y - mB1, rB2 = asB.z - mB2;
    float dsB = asB.w - 2.f * (asB.x * mB0 + asB.y * mB1 + asB.z * mB2) + mB3;

    float2 sA0 = __half22float2(*(__half2*)&svA.x);
    float2 sA1 = __half22float2(*(__half2*)&svA.y);
    float2 sB0 = __half22float2(*(__half2*)&svB.x);
    float2 sB1 = __half22float2(*(__half2*)&svB.y);

    float v0 = sA0.x + aA0 * inv + rA0 * w0.x + rA1 * w1.x + rA2 * w2.x + dsA * w3.x;
    float v1 = sA0.y + aA1 * inv + rA0 * w0.y + rA1 * w1.y + rA2 * w2.y + dsA * w3.y;
    float v2 = sA1.x + aA2 * inv + rA0 * w0.z + rA1 * w1.z + rA2 * w2.z + dsA * w3.z;
    float v3 = sA1.y + aA3 * inv + rA0 * w0.w + rA1 * w1.w + rA2 * w2.w + dsA * w3.w;
    float4 rA;
    rA.x = v0 > 0.f ? v0 : 0.2f * v0;
    rA.y = v1 > 0.f ? v1 : 0.2f * v1;
    rA.z = v2 > 0.f ? v2 : 0.2f * v2;
    rA.w = v3 > 0.f ? v3 : 0.2f * v3;
    __stcs((float4*)(out + (size_t)pA * 128 + 4 * lane), rA);

    float u0 = sB0.x + aB0 * inv + rB0 * w0.x + rB1 * w1.x + rB2 * w2.x + dsB * w3.x;
    float u1 = sB0.y + aB1 * inv + rB0 * w0.y + rB1 * w1.y + rB2 * w2.y + dsB * w3.y;
    float u2 = sB1.x + aB2 * inv + rB0 * w0.z + rB1 * w1.z + rB2 * w2.z + dsB * w3.z;
    float u3 = sB1.y + aB3 * inv + rB0 * w0.w + rB1 * w1.w + rB2 * w2.w + dsB * w3.w;
    float4 rB;
    rB.x = u0 > 0.f ? u0 : 0.2f * u0;
    rB.y = u1 > 0.f ? u1 : 0.2f * u1;
    rB.z = u2 > 0.f ? u2 : 0.2f * u2;
    rB.w = u3 > 0.f ? u3 : 0.2f * u3;
    __stcs((float4*)(out + (size_t)pB * 128 + 4 * lane), rB);
}

}  // namespace

extern "C" void kernel_launch(void* const* d_in, const int* in_sizes, int n_in,
                              void* d_out, int out_size) {
    const float* x   = (const float*)d_in[0];   // [8,16384,128]
    const float* pos = (const float*)d_in[1];   // [8,16384,3]
    const int*   idx = (const int*)d_in[2];     // [8,16384,16]
    const float* ws  = (const float*)d_in[3];   // [128,128]
    const float* we  = (const float*)d_in[4];   // [132,128]
    float* out = (float*)d_out;

    cudaFuncSetAttribute(prepass, cudaFuncAttributeMaxDynamicSharedMemorySize, SM2_TOTAL);
    prepack<<<136 + 512, 256>>>(ws, we, pos);
    prepass<<<148, 512, SM2_TOTAL>>>(x);
    gather<<<8192, 256>>>(idx, we, out);
}